// round 2
// baseline (speedup 1.0000x reference)
#include <cuda_runtime.h>
#include <math.h>

#define BB 128     // batch
#define DD 512     // hidden
#define GG 2048    // 4*D
#define VV 10000   // vocab
#define TT 20      // timesteps

// ---------------- device scratch (no allocation allowed) ----------------
__device__ float g_Mt[DD * GG];      // (512,2048)  fused input weights, transposed
__device__ float g_Mtmp[GG * DD];    // (2048,512)  W_ih0 @ W_enc
__device__ float g_Whh0t[DD * GG];   // (512,2048)
__device__ float g_Wih1t[DD * GG];
__device__ float g_Whh1t[DD * GG];
__device__ float g_WencT[DD * VV];   // (512,10000)
__device__ float g_H1[TT * BB * DD]; // layer-1 hidden history
__device__ float g_h0a[BB * DD];
__device__ float g_h0b[BB * DD];
__device__ float g_c0[BB * DD];
__device__ float g_c1[BB * DD];
__device__ float g_zero[BB * DD];
__device__ float g_bias0[GG];
__device__ float g_bias0f[GG];       // bias0 + W_ih0 @ b_enc
__device__ float g_bias1[GG];

// ---------------- init ----------------
__global__ void zero_state_kernel() {
    int i = blockIdx.x * blockDim.x + threadIdx.x;
    if (i < BB * DD) { g_c0[i] = 0.f; g_c1[i] = 0.f; g_zero[i] = 0.f; }
}

__global__ void bias_prep_kernel(const float* __restrict__ b_ih0, const float* __restrict__ b_hh0,
                                 const float* __restrict__ b_ih1, const float* __restrict__ b_hh1) {
    int g = blockIdx.x * blockDim.x + threadIdx.x;
    if (g < GG) {
        g_bias0[g] = b_ih0[g] + b_hh0[g];
        g_bias1[g] = b_ih1[g] + b_hh1[g];
    }
}

// bias0f[g] = bias0[g] + sum_v W_ih0[g,v]*b_enc[v]
__global__ void bfused_kernel(const float* __restrict__ W_ih0, const float* __restrict__ b_enc) {
    __shared__ float red[256];
    int g = blockIdx.x;
    float s = 0.f;
    for (int v = threadIdx.x; v < VV; v += 256)
        s += W_ih0[(size_t)g * VV + v] * b_enc[v];
    red[threadIdx.x] = s;
    __syncthreads();
    for (int o = 128; o > 0; o >>= 1) {
        if (threadIdx.x < o) red[threadIdx.x] += red[threadIdx.x + o];
        __syncthreads();
    }
    if (threadIdx.x == 0) g_bias0f[g] = g_bias0[g] + red[0];
}

// ---------------- transpose: src (R,C) -> dst (C,R) ----------------
__global__ void transpose_kernel(const float* __restrict__ src, float* __restrict__ dst,
                                 int R, int C) {
    __shared__ float tile[32][33];
    int c0 = blockIdx.x * 32, r0 = blockIdx.y * 32;
    int c = c0 + threadIdx.x;
    for (int i = threadIdx.y; i < 32; i += 8) {
        int r = r0 + i;
        if (r < R && c < C) tile[i][threadIdx.x] = src[(size_t)r * C + c];
    }
    __syncthreads();
    int r = r0 + threadIdx.x;
    for (int i = threadIdx.y; i < 32; i += 8) {
        int cc = c0 + i;
        if (cc < C && r < R) dst[(size_t)cc * R + r] = tile[threadIdx.x][i];
    }
}

// ---------------- tiled SGEMM: C(M,N) = A(M,K)@B(K,N) + bias[n] ----------------
// BM=BN=64, BK=16, 256 threads, 4x4 microtile. Requires M%64==0, K%16==0. N guarded.
__global__ __launch_bounds__(256) void sgemm_kernel(
    const float* __restrict__ A, const float* __restrict__ Bm,
    float* __restrict__ C, const float* __restrict__ bias,
    int M, int N, int K) {
    __shared__ float As[16][68];
    __shared__ float Bs[16][68];
    int m0 = blockIdx.y * 64, n0 = blockIdx.x * 64;
    int tid = threadIdx.x;
    int tx = tid & 15, ty = tid >> 4;
    int a_row = tid >> 2, a_k4 = (tid & 3) << 2;
    int b_k = tid >> 4, b_n = (tid & 15) << 2;

    float acc[4][4];
    #pragma unroll
    for (int i = 0; i < 4; i++)
        #pragma unroll
        for (int j = 0; j < 4; j++) acc[i][j] = 0.f;

    for (int kc = 0; kc < K; kc += 16) {
        float4 av = *(const float4*)&A[(size_t)(m0 + a_row) * K + kc + a_k4];
        As[a_k4 + 0][a_row] = av.x;
        As[a_k4 + 1][a_row] = av.y;
        As[a_k4 + 2][a_row] = av.z;
        As[a_k4 + 3][a_row] = av.w;

        int gn = n0 + b_n;
        const float* Bp = &Bm[(size_t)(kc + b_k) * N + gn];
        float4 bv;
        if (gn + 3 < N) {
            bv = *(const float4*)Bp;
        } else {
            bv.x = (gn + 0 < N) ? Bp[0] : 0.f;
            bv.y = (gn + 1 < N) ? Bp[1] : 0.f;
            bv.z = (gn + 2 < N) ? Bp[2] : 0.f;
            bv.w = (gn + 3 < N) ? Bp[3] : 0.f;
        }
        *(float4*)&Bs[b_k][b_n] = bv;
        __syncthreads();

        #pragma unroll
        for (int k = 0; k < 16; k++) {
            float4 a4 = *(const float4*)&As[k][ty << 2];
            float4 b4 = *(const float4*)&Bs[k][tx << 2];
            float a[4] = {a4.x, a4.y, a4.z, a4.w};
            float b[4] = {b4.x, b4.y, b4.z, b4.w};
            #pragma unroll
            for (int i = 0; i < 4; i++)
                #pragma unroll
                for (int j = 0; j < 4; j++)
                    acc[i][j] += a[i] * b[j];
        }
        __syncthreads();
    }

    #pragma unroll
    for (int i = 0; i < 4; i++) {
        int m = m0 + (ty << 2) + i;
        #pragma unroll
        for (int j = 0; j < 4; j++) {
            int n = n0 + (tx << 2) + j;
            if (n < N) {
                float v = acc[i][j];
                if (bias) v += bias[n];
                C[(size_t)m * N + n] = v;
            }
        }
    }
}

// ---------------- fused LSTM cell ----------------
// gates(B,2048) = x(B,512)@Wxt(512,2048) + h(B,512)@Wht(512,2048) + bias
// Weight layout in gmem: Wt[k*2048 + gate*512 + d]; smem re-packed as [k][d][gate]
// so each thread owns all 4 gates of one (b,d) and applies activations locally.
// Block: 16 batch rows x 32 d's. Grid: (512/32, 128/16) = (16,8). 256 threads.
__global__ __launch_bounds__(256) void lstm_cell_kernel(
    const float* __restrict__ x,    // (B,512) or nullptr
    const float* __restrict__ Wxt,  // (512,2048)
    const float* __restrict__ h,    // (B,512)
    const float* __restrict__ Wht,  // (512,2048)
    const float* __restrict__ bias, // (2048) [i f g o]
    float* __restrict__ c,          // (B,512) in/out
    float* __restrict__ hout)       // (B,512)
{
    __shared__ float As[16][17];     // [k][row]
    __shared__ float Bs[16 * 128];   // [k][d][gate]
    int b0 = blockIdx.y * 16;
    int d0 = blockIdx.x * 32;
    int tid = threadIdx.x;
    int tr = tid >> 5, td = tid & 31;
    int lk = tid & 15, lm = tid >> 4;

    float acc[2][4];
    #pragma unroll
    for (int r = 0; r < 2; r++)
        #pragma unroll
        for (int j = 0; j < 4; j++) acc[r][j] = 0.f;

    for (int pass = 0; pass < 2; pass++) {
        const float* Am;
        const float* Wm;
        if (pass == 0) { Am = h; Wm = Wht; }
        else {
            if (x == nullptr) break;
            Am = x; Wm = Wxt;
        }
        for (int kc = 0; kc < DD; kc += 16) {
            As[lk][lm] = Am[(size_t)(b0 + lm) * DD + kc + lk];
            #pragma unroll
            for (int i = 0; i < 8; i++) {
                int idx = i * 256 + tid;
                int k = idx >> 7;
                int rem = idx & 127;
                int gate = rem >> 5;
                int dd = rem & 31;
                Bs[k * 128 + dd * 4 + gate] =
                    Wm[(size_t)(kc + k) * GG + gate * DD + d0 + dd];
            }
            __syncthreads();
            #pragma unroll
            for (int k = 0; k < 16; k++) {
                float a0 = As[k][tr * 2];
                float a1 = As[k][tr * 2 + 1];
                float4 b4 = *(const float4*)&Bs[k * 128 + td * 4];
                acc[0][0] += a0 * b4.x; acc[0][1] += a0 * b4.y;
                acc[0][2] += a0 * b4.z; acc[0][3] += a0 * b4.w;
                acc[1][0] += a1 * b4.x; acc[1][1] += a1 * b4.y;
                acc[1][2] += a1 * b4.z; acc[1][3] += a1 * b4.w;
            }
            __syncthreads();
        }
    }

    int d = d0 + td;
    float bi = bias[d];
    float bf = bias[DD + d];
    float bg = bias[2 * DD + d];
    float bo = bias[3 * DD + d];
    #pragma unroll
    for (int r = 0; r < 2; r++) {
        int b = b0 + tr * 2 + r;
        float ig = 1.f / (1.f + expf(-(acc[r][0] + bi)));
        float fg = 1.f / (1.f + expf(-(acc[r][1] + bf)));
        float gg = tanhf(acc[r][2] + bg);
        float og = 1.f / (1.f + expf(-(acc[r][3] + bo)));
        float cn = fg * c[(size_t)b * DD + d] + ig * gg;
        c[(size_t)b * DD + d] = cn;
        hout[(size_t)b * DD + d] = og * tanhf(cn);
    }
}

// ---------------- host ----------------
extern "C" void kernel_launch(void* const* d_in, const int* in_sizes, int n_in,
                              void* d_out, int out_size) {
    const float* input_ = (const float*)d_in[0];
    const float* W_ih0  = (const float*)d_in[1];
    const float* W_hh0  = (const float*)d_in[2];
    const float* b_ih0  = (const float*)d_in[3];
    const float* b_hh0  = (const float*)d_in[4];
    const float* W_ih1  = (const float*)d_in[5];
    const float* W_hh1  = (const float*)d_in[6];
    const float* b_ih1  = (const float*)d_in[7];
    const float* b_hh1  = (const float*)d_in[8];
    const float* W_enc  = (const float*)d_in[9];
    const float* b_enc  = (const float*)d_in[10];
    float* out = (float*)d_out;

    float *p_Mt, *p_Mtmp, *p_Whh0t, *p_Wih1t, *p_Whh1t, *p_WencT, *p_H1;
    float *p_h0a, *p_h0b, *p_c0, *p_c1, *p_zero, *p_bias0, *p_bias0f, *p_bias1;
    cudaGetSymbolAddress((void**)&p_Mt,     g_Mt);
    cudaGetSymbolAddress((void**)&p_Mtmp,   g_Mtmp);
    cudaGetSymbolAddress((void**)&p_Whh0t,  g_Whh0t);
    cudaGetSymbolAddress((void**)&p_Wih1t,  g_Wih1t);
    cudaGetSymbolAddress((void**)&p_Whh1t,  g_Whh1t);
    cudaGetSymbolAddress((void**)&p_WencT,  g_WencT);
    cudaGetSymbolAddress((void**)&p_H1,     g_H1);
    cudaGetSymbolAddress((void**)&p_h0a,    g_h0a);
    cudaGetSymbolAddress((void**)&p_h0b,    g_h0b);
    cudaGetSymbolAddress((void**)&p_c0,     g_c0);
    cudaGetSymbolAddress((void**)&p_c1,     g_c1);
    cudaGetSymbolAddress((void**)&p_zero,   g_zero);
    cudaGetSymbolAddress((void**)&p_bias0,  g_bias0);
    cudaGetSymbolAddress((void**)&p_bias0f, g_bias0f);
    cudaGetSymbolAddress((void**)&p_bias1,  g_bias1);

    // ---- prep ----
    zero_state_kernel<<<(BB * DD + 255) / 256, 256>>>();
    bias_prep_kernel<<<(GG + 255) / 256, 256>>>(b_ih0, b_hh0, b_ih1, b_hh1);
    bfused_kernel<<<GG, 256>>>(W_ih0, b_enc);

    dim3 tb(32, 8);
    transpose_kernel<<<dim3(512 / 32, 2048 / 32), tb>>>(W_hh0, p_Whh0t, GG, DD);
    transpose_kernel<<<dim3(512 / 32, 2048 / 32), tb>>>(W_ih1, p_Wih1t, GG, DD);
    transpose_kernel<<<dim3(512 / 32, 2048 / 32), tb>>>(W_hh1, p_Whh1t, GG, DD);
    transpose_kernel<<<dim3(512 / 32, (VV + 31) / 32), tb>>>(W_enc, p_WencT, VV, DD);

    // M = W_ih0 (2048,10000) @ W_enc (10000,512) -> Mtmp (2048,512) -> Mt (512,2048)
    sgemm_kernel<<<dim3(DD / 64, GG / 64), 256>>>(W_ih0, W_enc, p_Mtmp, nullptr, GG, DD, VV);
    transpose_kernel<<<dim3(512 / 32, 2048 / 32), tb>>>(p_Mtmp, p_Mt, GG, DD);

    // ---- sequential recurrence ----
    dim3 cell_grid(DD / 32, BB / 16);
    const float* h0_in = input_;
    float* h0_out = p_h0a;
    for (int t = 0; t < TT; t++) {
        const float* x0    = (t == 0) ? nullptr : (p_H1 + (size_t)(t - 1) * BB * DD);
        const float* bias0 = (t == 0) ? p_bias0 : p_bias0f;
        lstm_cell_kernel<<<cell_grid, 256>>>(x0, p_Mt, h0_in, p_Whh0t, bias0, p_c0, h0_out);

        const float* h1_in = (t == 0) ? p_zero : (p_H1 + (size_t)(t - 1) * BB * DD);
        lstm_cell_kernel<<<cell_grid, 256>>>(h0_out, p_Wih1t, h1_in, p_Whh1t, p_bias1,
                                             p_c1, p_H1 + (size_t)t * BB * DD);

        h0_in = h0_out;
        h0_out = (h0_out == p_h0a) ? p_h0b : p_h0a;
    }

    // ---- batched logits: OUT(2560,10000) = H1(2560,512) @ WencT(512,10000) + b_enc ----
    sgemm_kernel<<<dim3((VV + 63) / 64, (TT * BB) / 64), 256>>>(
        p_H1, p_WencT, out, b_enc, TT * BB, VV, DD);
}

// round 4
// speedup vs baseline: 1.4099x; 1.4099x over previous
#include <cuda_runtime.h>
#include <cuda_bf16.h>
#include <math.h>
#include <stdint.h>

#define BB 128     // batch
#define DD 512     // hidden
#define GG 2048    // 4*D
#define VV 10000   // vocab
#define TT 20      // timesteps

// ---------------- device scratch (no allocation allowed) ----------------
__device__ float g_Mt[DD * GG];      // (512,2048)  fused input weights, transposed
__device__ float g_Mtmp[GG * DD];    // (2048,512)  W_ih0 @ W_enc
__device__ float g_Whh0t[DD * GG];
__device__ float g_Wih1t[DD * GG];
__device__ float g_Whh1t[DD * GG];
__device__ float g_WencT[DD * VV];   // (512,10000) fp32 transpose of W_enc
__device__ float g_H1[TT * BB * DD]; // layer-1 hidden history (fp32)
__device__ float g_h0a[BB * DD];
__device__ float g_h0b[BB * DD];
__device__ float g_c0[BB * DD];
__device__ float g_c1[BB * DD];
__device__ float g_zero[BB * DD];
__device__ float g_bias0[GG];
__device__ float g_bias0f[GG];
__device__ float g_bias1[GG];
// bf16 hi/lo decompositions for tensor-core GEMMs
__device__ __nv_bfloat16 g_A1hi[(size_t)GG * VV];  // W_ih0 (2048,10000)
__device__ __nv_bfloat16 g_A1lo[(size_t)GG * VV];
__device__ __nv_bfloat16 g_B1hi[(size_t)DD * VV];  // WencT rows=512, K=10000
__device__ __nv_bfloat16 g_B1lo[(size_t)DD * VV];
__device__ __nv_bfloat16 g_B2hi[(size_t)VV * DD];  // W_enc rows=10000, K=512
__device__ __nv_bfloat16 g_B2lo[(size_t)VV * DD];
__device__ __nv_bfloat16 g_H1hi[TT * BB * DD];
__device__ __nv_bfloat16 g_H1lo[TT * BB * DD];

// =========================================================================
// helpers
// =========================================================================
__device__ __forceinline__ uint32_t smem_u32(const void* p) {
    uint32_t a;
    asm("{ .reg .u64 t; cvta.to.shared.u64 t, %1; cvt.u32.u64 %0, t; }" : "=r"(a) : "l"(p));
    return a;
}
#define SWZ128(o) ((o) ^ (((o) >> 3) & 0x70))

__device__ __forceinline__ void ldsm_x4(uint32_t* r, uint32_t addr) {
    asm volatile("ldmatrix.sync.aligned.m8n8.x4.shared.b16 {%0,%1,%2,%3}, [%4];"
                 : "=r"(r[0]), "=r"(r[1]), "=r"(r[2]), "=r"(r[3]) : "r"(addr));
}
__device__ __forceinline__ void mma16816(float* d, const uint32_t* a, const uint32_t* b) {
    asm volatile(
        "mma.sync.aligned.m16n8k16.row.col.f32.bf16.bf16.f32 "
        "{%0,%1,%2,%3}, {%4,%5,%6,%7}, {%8,%9}, {%0,%1,%2,%3};"
        : "+f"(d[0]), "+f"(d[1]), "+f"(d[2]), "+f"(d[3])
        : "r"(a[0]), "r"(a[1]), "r"(a[2]), "r"(a[3]), "r"(b[0]), "r"(b[1]));
}
__device__ __forceinline__ void cp_async16(uint32_t daddr, const void* g, unsigned sz) {
    asm volatile("cp.async.cg.shared.global [%0], [%1], 16, %2;"
                 :: "r"(daddr), "l"(g), "r"(sz));
}
#define CP_COMMIT() asm volatile("cp.async.commit_group;" ::: "memory")
#define CP_WAIT(n)  asm volatile("cp.async.wait_group %0;" :: "n"(n) : "memory")

// =========================================================================
// small prep kernels
// =========================================================================
__global__ void zero_state_kernel() {
    int i = blockIdx.x * blockDim.x + threadIdx.x;
    if (i < BB * DD) { g_c0[i] = 0.f; g_c1[i] = 0.f; g_zero[i] = 0.f; }
}

__global__ void bias_prep_kernel(const float* __restrict__ b_ih0, const float* __restrict__ b_hh0,
                                 const float* __restrict__ b_ih1, const float* __restrict__ b_hh1) {
    int g = blockIdx.x * blockDim.x + threadIdx.x;
    if (g < GG) {
        g_bias0[g] = b_ih0[g] + b_hh0[g];
        g_bias1[g] = b_ih1[g] + b_hh1[g];
    }
}

__global__ void bfused_kernel(const float* __restrict__ W_ih0, const float* __restrict__ b_enc) {
    __shared__ float red[256];
    int g = blockIdx.x;
    float s = 0.f;
    for (int v = threadIdx.x; v < VV; v += 256)
        s += W_ih0[(size_t)g * VV + v] * b_enc[v];
    red[threadIdx.x] = s;
    __syncthreads();
    for (int o = 128; o > 0; o >>= 1) {
        if (threadIdx.x < o) red[threadIdx.x] += red[threadIdx.x + o];
        __syncthreads();
    }
    if (threadIdx.x == 0) g_bias0f[g] = g_bias0[g] + red[0];
}

__global__ void transpose_kernel(const float* __restrict__ src, float* __restrict__ dst,
                                 int R, int C) {
    __shared__ float tile[32][33];
    int c0 = blockIdx.x * 32, r0 = blockIdx.y * 32;
    int c = c0 + threadIdx.x;
    for (int i = threadIdx.y; i < 32; i += 8) {
        int r = r0 + i;
        if (r < R && c < C) tile[i][threadIdx.x] = src[(size_t)r * C + c];
    }
    __syncthreads();
    int r = r0 + threadIdx.x;
    for (int i = threadIdx.y; i < 32; i += 8) {
        int cc = c0 + i;
        if (cc < C && r < R) dst[(size_t)cc * R + r] = tile[threadIdx.x][i];
    }
}

// fp32 -> (bf16 hi, bf16 lo).  n must be divisible by 4.
__global__ void split_bf16_kernel(const float* __restrict__ src,
                                  __nv_bfloat16* __restrict__ hi,
                                  __nv_bfloat16* __restrict__ lo, int n) {
    int i = (blockIdx.x * blockDim.x + threadIdx.x) * 4;
    if (i < n) {
        float4 v = *(const float4*)(src + i);
        float vv[4] = {v.x, v.y, v.z, v.w};
        __nv_bfloat16 h[4], l[4];
        #pragma unroll
        for (int j = 0; j < 4; j++) {
            h[j] = __float2bfloat16_rn(vv[j]);
            l[j] = __float2bfloat16_rn(vv[j] - __bfloat162float(h[j]));
        }
        *(uint2*)(hi + i) = *(uint2*)h;
        *(uint2*)(lo + i) = *(uint2*)l;
    }
}

// =========================================================================
// mma.sync bf16x3 GEMM:  C(M,N) = sum_k A(M,K) * B(N,K)^T  (+ bias[n])
// A,B given as (hi,lo) bf16 pairs, K-major rows. TILE 128x128, BK=64,
// double-buffered cp.async, 8 warps (4m x 2n), warp tile 32x64.
// grid = (ceil(N/128), M/128), block = 256.
// =========================================================================
#define GEMM_SMEM (2 * 4 * 16384)   // 131072

__global__ __launch_bounds__(256) void gemm_bf16x3_kernel(
    const __nv_bfloat16* __restrict__ Ahi, const __nv_bfloat16* __restrict__ Alo,
    const __nv_bfloat16* __restrict__ Bhi, const __nv_bfloat16* __restrict__ Blo,
    float* __restrict__ C, const float* __restrict__ bias,
    int Mtot, int Ntot, int Ktot)
{
    extern __shared__ char smem[];
    const uint32_t sb = smem_u32(smem);
    const int tid = threadIdx.x, wid = tid >> 5, lane = tid & 31;
    const int wm = wid & 3, wn = wid >> 2;       // 4 x 2 warp grid
    const int m0 = blockIdx.y * 128, n0 = blockIdx.x * 128;
    const int NT = (Ktot + 63) / 64;

    float acc[2][8][4];
    #pragma unroll
    for (int mt = 0; mt < 2; mt++)
        #pragma unroll
        for (int nt = 0; nt < 8; nt++)
            #pragma unroll
            for (int j = 0; j < 4; j++) acc[mt][nt][j] = 0.f;

    // ---- async load of one K-chunk into buffer `buf` ----
    auto load_chunk = [&](int kt, int buf) {
        const int kc = kt * 64;
        #pragma unroll
        for (int w = 0; w < 4; w++) {
            const __nv_bfloat16* src = (w == 0) ? Ahi : (w == 1) ? Alo : (w == 2) ? Bhi : Blo;
            const int rbase = (w < 2) ? m0 : n0;
            const int rlim  = (w < 2) ? Mtot : Ntot;
            const uint32_t tdst = sb + buf * 65536 + w * 16384;
            #pragma unroll
            for (int it = 0; it < 4; it++) {
                int i = it * 256 + tid;
                int r = i >> 3, c16 = i & 7;
                int gr = rbase + r, gk = kc + c16 * 8;
                bool inb = (gr < rlim) && (gk < Ktot);
                const void* g = src + (inb ? ((size_t)gr * Ktot + gk) : 0);
                cp_async16(tdst + SWZ128(r * 128 + c16 * 16), g, inb ? 16u : 0u);
            }
        }
        CP_COMMIT();
    };

    load_chunk(0, 0);

    const int g8 = lane >> 3, rg = lane & 7;

    for (int kt = 0; kt < NT; kt++) {
        const int buf = kt & 1;
        if (kt + 1 < NT) {
            load_chunk(kt + 1, buf ^ 1);
            CP_WAIT(1);
        } else {
            CP_WAIT(0);
        }
        __syncthreads();

        const uint32_t bAh = sb + buf * 65536;
        const uint32_t bAl = bAh + 16384;
        const uint32_t bBh = bAh + 32768;
        const uint32_t bBl = bAh + 49152;

        #pragma unroll
        for (int kk = 0; kk < 4; kk++) {
            const int kb = kk * 32;
            uint32_t ah[2][4], al[2][4], bh[8][2], bl[8][2];
            #pragma unroll
            for (int mt = 0; mt < 2; mt++) {
                int row = wm * 32 + mt * 16 + (g8 & 1) * 8 + rg;
                uint32_t off = SWZ128(row * 128 + kb + (g8 >> 1) * 16);
                ldsm_x4(ah[mt], bAh + off);
                ldsm_x4(al[mt], bAl + off);
            }
            #pragma unroll
            for (int p = 0; p < 4; p++) {
                int rowb = wn * 64 + p * 16 + (g8 >> 1) * 8 + rg;
                uint32_t off = SWZ128(rowb * 128 + kb + (g8 & 1) * 16);
                uint32_t t[4];
                ldsm_x4(t, bBh + off);
                bh[2 * p][0] = t[0]; bh[2 * p][1] = t[1];
                bh[2 * p + 1][0] = t[2]; bh[2 * p + 1][1] = t[3];
                ldsm_x4(t, bBl + off);
                bl[2 * p][0] = t[0]; bl[2 * p][1] = t[1];
                bl[2 * p + 1][0] = t[2]; bl[2 * p + 1][1] = t[3];
            }
            #pragma unroll
            for (int mt = 0; mt < 2; mt++)
                #pragma unroll
                for (int nt = 0; nt < 8; nt++) {
                    mma16816(acc[mt][nt], ah[mt], bh[nt]);
                    mma16816(acc[mt][nt], ah[mt], bl[nt]);
                    mma16816(acc[mt][nt], al[mt], bh[nt]);
                }
        }
        __syncthreads();
    }

    // ---- epilogue: direct stores (cols even; Ntot even -> float2 safe) ----
    #pragma unroll
    for (int mt = 0; mt < 2; mt++) {
        int row = m0 + wm * 32 + mt * 16 + (lane >> 2);
        #pragma unroll
        for (int nt = 0; nt < 8; nt++) {
            int col = n0 + wn * 64 + nt * 8 + (lane & 3) * 2;
            if (col < Ntot) {
                float b0 = 0.f, b1 = 0.f;
                if (bias) { b0 = bias[col]; b1 = bias[col + 1]; }
                float2 v0 = make_float2(acc[mt][nt][0] + b0, acc[mt][nt][1] + b1);
                float2 v1 = make_float2(acc[mt][nt][2] + b0, acc[mt][nt][3] + b1);
                *(float2*)&C[(size_t)row * Ntot + col] = v0;
                *(float2*)&C[(size_t)(row + 8) * Ntot + col] = v1;
            }
        }
    }
}

// =========================================================================
// fused LSTM cell (fp32 SIMT) — unchanged
// =========================================================================
__global__ __launch_bounds__(256) void lstm_cell_kernel(
    const float* __restrict__ x, const float* __restrict__ Wxt,
    const float* __restrict__ h, const float* __restrict__ Wht,
    const float* __restrict__ bias, float* __restrict__ c, float* __restrict__ hout)
{
    __shared__ float As[16][17];
    __shared__ float Bs[16 * 128];
    int b0 = blockIdx.y * 16;
    int d0 = blockIdx.x * 32;
    int tid = threadIdx.x;
    int tr = tid >> 5, td = tid & 31;
    int lk = tid & 15, lm = tid >> 4;

    float acc[2][4];
    #pragma unroll
    for (int r = 0; r < 2; r++)
        #pragma unroll
        for (int j = 0; j < 4; j++) acc[r][j] = 0.f;

    for (int pass = 0; pass < 2; pass++) {
        const float* Am;
        const float* Wm;
        if (pass == 0) { Am = h; Wm = Wht; }
        else {
            if (x == nullptr) break;
            Am = x; Wm = Wxt;
        }
        for (int kc = 0; kc < DD; kc += 16) {
            As[lk][lm] = Am[(size_t)(b0 + lm) * DD + kc + lk];
            #pragma unroll
            for (int i = 0; i < 8; i++) {
                int idx = i * 256 + tid;
                int k = idx >> 7;
                int rem = idx & 127;
                int gate = rem >> 5;
                int dd = rem & 31;
                Bs[k * 128 + dd * 4 + gate] =
                    Wm[(size_t)(kc + k) * GG + gate * DD + d0 + dd];
            }
            __syncthreads();
            #pragma unroll
            for (int k = 0; k < 16; k++) {
                float a0 = As[k][tr * 2];
                float a1 = As[k][tr * 2 + 1];
                float4 b4 = *(const float4*)&Bs[k * 128 + td * 4];
                acc[0][0] += a0 * b4.x; acc[0][1] += a0 * b4.y;
                acc[0][2] += a0 * b4.z; acc[0][3] += a0 * b4.w;
                acc[1][0] += a1 * b4.x; acc[1][1] += a1 * b4.y;
                acc[1][2] += a1 * b4.z; acc[1][3] += a1 * b4.w;
            }
            __syncthreads();
        }
    }

    int d = d0 + td;
    float bi = bias[d];
    float bf = bias[DD + d];
    float bg = bias[2 * DD + d];
    float bo = bias[3 * DD + d];
    #pragma unroll
    for (int r = 0; r < 2; r++) {
        int b = b0 + tr * 2 + r;
        float ig = 1.f / (1.f + expf(-(acc[r][0] + bi)));
        float fg = 1.f / (1.f + expf(-(acc[r][1] + bf)));
        float gg = tanhf(acc[r][2] + bg);
        float og = 1.f / (1.f + expf(-(acc[r][3] + bo)));
        float cn = fg * c[(size_t)b * DD + d] + ig * gg;
        c[(size_t)b * DD + d] = cn;
        hout[(size_t)b * DD + d] = og * tanhf(cn);
    }
}

// =========================================================================
// host
// =========================================================================
extern "C" void kernel_launch(void* const* d_in, const int* in_sizes, int n_in,
                              void* d_out, int out_size) {
    const float* input_ = (const float*)d_in[0];
    const float* W_ih0  = (const float*)d_in[1];
    const float* W_hh0  = (const float*)d_in[2];
    const float* b_ih0  = (const float*)d_in[3];
    const float* b_hh0  = (const float*)d_in[4];
    const float* W_ih1  = (const float*)d_in[5];
    const float* W_hh1  = (const float*)d_in[6];
    const float* b_ih1  = (const float*)d_in[7];
    const float* b_hh1  = (const float*)d_in[8];
    const float* W_enc  = (const float*)d_in[9];
    const float* b_enc  = (const float*)d_in[10];
    float* out = (float*)d_out;

    float *p_Mt, *p_Mtmp, *p_Whh0t, *p_Wih1t, *p_Whh1t, *p_WencT, *p_H1;
    float *p_h0a, *p_h0b, *p_c0, *p_c1, *p_zero, *p_bias0, *p_bias0f, *p_bias1;
    __nv_bfloat16 *p_A1hi, *p_A1lo, *p_B1hi, *p_B1lo, *p_B2hi, *p_B2lo, *p_H1hi, *p_H1lo;
    cudaGetSymbolAddress((void**)&p_Mt,     g_Mt);
    cudaGetSymbolAddress((void**)&p_Mtmp,   g_Mtmp);
    cudaGetSymbolAddress((void**)&p_Whh0t,  g_Whh0t);
    cudaGetSymbolAddress((void**)&p_Wih1t,  g_Wih1t);
    cudaGetSymbolAddress((void**)&p_Whh1t,  g_Whh1t);
    cudaGetSymbolAddress((void**)&p_WencT,  g_WencT);
    cudaGetSymbolAddress((void**)&p_H1,     g_H1);
    cudaGetSymbolAddress((void**)&p_h0a,    g_h0a);
    cudaGetSymbolAddress((void**)&p_h0b,    g_h0b);
    cudaGetSymbolAddress((void**)&p_c0,     g_c0);
    cudaGetSymbolAddress((void**)&p_c1,     g_c1);
    cudaGetSymbolAddress((void**)&p_zero,   g_zero);
    cudaGetSymbolAddress((void**)&p_bias0,  g_bias0);
    cudaGetSymbolAddress((void**)&p_bias0f, g_bias0f);
    cudaGetSymbolAddress((void**)&p_bias1,  g_bias1);
    cudaGetSymbolAddress((void**)&p_A1hi,   g_A1hi);
    cudaGetSymbolAddress((void**)&p_A1lo,   g_A1lo);
    cudaGetSymbolAddress((void**)&p_B1hi,   g_B1hi);
    cudaGetSymbolAddress((void**)&p_B1lo,   g_B1lo);
    cudaGetSymbolAddress((void**)&p_B2hi,   g_B2hi);
    cudaGetSymbolAddress((void**)&p_B2lo,   g_B2lo);
    cudaGetSymbolAddress((void**)&p_H1hi,   g_H1hi);
    cudaGetSymbolAddress((void**)&p_H1lo,   g_H1lo);

    cudaFuncSetAttribute(gemm_bf16x3_kernel,
                         cudaFuncAttributeMaxDynamicSharedMemorySize, GEMM_SMEM);

    // ---- prep ----
    zero_state_kernel<<<(BB * DD + 255) / 256, 256>>>();
    bias_prep_kernel<<<(GG + 255) / 256, 256>>>(b_ih0, b_hh0, b_ih1, b_hh1);
    bfused_kernel<<<GG, 256>>>(W_ih0, b_enc);

    dim3 tb(32, 8);
    transpose_kernel<<<dim3(512 / 32, 2048 / 32), tb>>>(W_hh0, p_Whh0t, GG, DD);
    transpose_kernel<<<dim3(512 / 32, 2048 / 32), tb>>>(W_ih1, p_Wih1t, GG, DD);
    transpose_kernel<<<dim3(512 / 32, 2048 / 32), tb>>>(W_hh1, p_Whh1t, GG, DD);
    transpose_kernel<<<dim3(512 / 32, (VV + 31) / 32), tb>>>(W_enc, p_WencT, VV, DD);

    // bf16 hi/lo splits
    {
        int n1 = GG * VV;   // W_ih0
        split_bf16_kernel<<<(n1 / 4 + 255) / 256, 256>>>(W_ih0, p_A1hi, p_A1lo, n1);
        int n2 = DD * VV;   // WencT
        split_bf16_kernel<<<(n2 / 4 + 255) / 256, 256>>>(p_WencT, p_B1hi, p_B1lo, n2);
        int n3 = VV * DD;   // W_enc
        split_bf16_kernel<<<(n3 / 4 + 255) / 256, 256>>>(W_enc, p_B2hi, p_B2lo, n3);
    }

    // GEMM1: Mtmp(2048,512) = W_ih0(2048,10000) @ WencT(512,10000)^T   [bf16x3 HMMA]
    gemm_bf16x3_kernel<<<dim3(DD / 128, GG / 128), 256, GEMM_SMEM>>>(
        p_A1hi, p_A1lo, p_B1hi, p_B1lo, p_Mtmp, nullptr, GG, DD, VV);
    transpose_kernel<<<dim3(512 / 32, 2048 / 32), tb>>>(p_Mtmp, p_Mt, GG, DD);

    // ---- sequential recurrence (fp32 SIMT cells) ----
    dim3 cell_grid(DD / 32, BB / 16);
    const float* h0_in = input_;
    float* h0_out = p_h0a;
    for (int t = 0; t < TT; t++) {
        const float* x0    = (t == 0) ? nullptr : (p_H1 + (size_t)(t - 1) * BB * DD);
        const float* bias0 = (t == 0) ? p_bias0 : p_bias0f;
        lstm_cell_kernel<<<cell_grid, 256>>>(x0, p_Mt, h0_in, p_Whh0t, bias0, p_c0, h0_out);

        const float* h1_in = (t == 0) ? p_zero : (p_H1 + (size_t)(t - 1) * BB * DD);
        lstm_cell_kernel<<<cell_grid, 256>>>(h0_out, p_Wih1t, h1_in, p_Whh1t, p_bias1,
                                             p_c1, p_H1 + (size_t)t * BB * DD);

        h0_in = h0_out;
        h0_out = (h0_out == p_h0a) ? p_h0b : p_h0a;
    }

    // split H1 -> bf16 hi/lo
    {
        int n = TT * BB * DD;
        split_bf16_kernel<<<(n / 4 + 255) / 256, 256>>>(p_H1, p_H1hi, p_H1lo, n);
    }

    // GEMM2: OUT(2560,10000) = H1(2560,512) @ W_enc(10000,512)^T + b_enc  [bf16x3 HMMA]
    gemm_bf16x3_kernel<<<dim3((VV + 127) / 128, (TT * BB) / 128), 256, GEMM_SMEM>>>(
        p_H1hi, p_H1lo, p_B2hi, p_B2lo, out, b_enc, TT * BB, VV, DD);
}

// round 5
// speedup vs baseline: 3.1803x; 2.2557x over previous
#include <cuda_runtime.h>
#include <cuda_bf16.h>
#include <math.h>
#include <stdint.h>

#define BB 128     // batch
#define DD 512     // hidden
#define GG 2048    // 4*D
#define VV 10000   // vocab
#define TT 20      // timesteps

// ---------------- device scratch (no allocation allowed) ----------------
__device__ float g_Mtmp[GG * DD];    // (2048,512)  W_ih0 @ W_enc (fp32)
__device__ float g_WencT[DD * VV];   // (512,10000) fp32 transpose of W_enc
__device__ float g_c0[BB * DD];
__device__ float g_c1[BB * DD];
__device__ float g_bias0[GG];
__device__ float g_bias0f[GG];
__device__ float g_bias1[GG];
// bf16 hi/lo operand buffers
__device__ __nv_bfloat16 g_A1hi[(size_t)GG * VV];  // W_ih0 (2048,10000)
__device__ __nv_bfloat16 g_A1lo[(size_t)GG * VV];
__device__ __nv_bfloat16 g_B1hi[(size_t)DD * VV];  // WencT rows=512, K=10000
__device__ __nv_bfloat16 g_B1lo[(size_t)DD * VV];
__device__ __nv_bfloat16 g_B2hi[(size_t)VV * DD];  // W_enc rows=10000, K=512
__device__ __nv_bfloat16 g_B2lo[(size_t)VV * DD];
__device__ __nv_bfloat16 g_H1hi[TT * BB * DD];     // h1 history (cells write, GEMM2 reads)
__device__ __nv_bfloat16 g_H1lo[TT * BB * DD];
// fused, gate-interleaved cell weights: (2048 rows n'=d*4+gate, K=1024 = [x|h])
__device__ __nv_bfloat16 g_Wc0hi[(size_t)GG * 1024];
__device__ __nv_bfloat16 g_Wc0lo[(size_t)GG * 1024];
__device__ __nv_bfloat16 g_Wc1hi[(size_t)GG * 1024];
__device__ __nv_bfloat16 g_Wc1lo[(size_t)GG * 1024];
// h0 double buffers + zero-h1 (bf16 hi/lo)
__device__ __nv_bfloat16 g_h0hiA[BB * DD], g_h0loA[BB * DD];
__device__ __nv_bfloat16 g_h0hiB[BB * DD], g_h0loB[BB * DD];
__device__ __nv_bfloat16 g_h1zhi[BB * DD], g_h1zlo[BB * DD];

// =========================================================================
// helpers
// =========================================================================
__device__ __forceinline__ uint32_t smem_u32(const void* p) {
    uint32_t a;
    asm("{ .reg .u64 t; cvta.to.shared.u64 t, %1; cvt.u32.u64 %0, t; }" : "=r"(a) : "l"(p));
    return a;
}
#define SWZ128(o) ((o) ^ (((o) >> 3) & 0x70))

__device__ __forceinline__ void ldsm_x4(uint32_t* r, uint32_t addr) {
    asm volatile("ldmatrix.sync.aligned.m8n8.x4.shared.b16 {%0,%1,%2,%3}, [%4];"
                 : "=r"(r[0]), "=r"(r[1]), "=r"(r[2]), "=r"(r[3]) : "r"(addr));
}
__device__ __forceinline__ void mma16816(float* d, const uint32_t* a, const uint32_t* b) {
    asm volatile(
        "mma.sync.aligned.m16n8k16.row.col.f32.bf16.bf16.f32 "
        "{%0,%1,%2,%3}, {%4,%5,%6,%7}, {%8,%9}, {%0,%1,%2,%3};"
        : "+f"(d[0]), "+f"(d[1]), "+f"(d[2]), "+f"(d[3])
        : "r"(a[0]), "r"(a[1]), "r"(a[2]), "r"(a[3]), "r"(b[0]), "r"(b[1]));
}
__device__ __forceinline__ void cp_async16(uint32_t daddr, const void* g, unsigned sz) {
    asm volatile("cp.async.cg.shared.global [%0], [%1], 16, %2;"
                 :: "r"(daddr), "l"(g), "r"(sz));
}
#define CP_COMMIT() asm volatile("cp.async.commit_group;" ::: "memory")
#define CP_WAIT(n)  asm volatile("cp.async.wait_group %0;" :: "n"(n) : "memory")

// =========================================================================
// prep kernels
// =========================================================================
__global__ void zero_state_kernel() {
    int i = blockIdx.x * blockDim.x + threadIdx.x;
    if (i < BB * DD) {
        g_c0[i] = 0.f; g_c1[i] = 0.f;
        g_h1zhi[i] = __float2bfloat16_rn(0.f);
        g_h1zlo[i] = __float2bfloat16_rn(0.f);
    }
}

__global__ void bias_prep_kernel(const float* __restrict__ b_ih0, const float* __restrict__ b_hh0,
                                 const float* __restrict__ b_ih1, const float* __restrict__ b_hh1) {
    int g = blockIdx.x * blockDim.x + threadIdx.x;
    if (g < GG) {
        g_bias0[g] = b_ih0[g] + b_hh0[g];
        g_bias1[g] = b_ih1[g] + b_hh1[g];
    }
}

__global__ void bfused_kernel(const float* __restrict__ W_ih0, const float* __restrict__ b_enc) {
    __shared__ float red[256];
    int g = blockIdx.x;
    float s = 0.f;
    for (int v = threadIdx.x; v < VV; v += 256)
        s += W_ih0[(size_t)g * VV + v] * b_enc[v];
    red[threadIdx.x] = s;
    __syncthreads();
    for (int o = 128; o > 0; o >>= 1) {
        if (threadIdx.x < o) red[threadIdx.x] += red[threadIdx.x + o];
        __syncthreads();
    }
    if (threadIdx.x == 0) g_bias0f[g] = g_bias0[g] + red[0];
}

__global__ void transpose_kernel(const float* __restrict__ src, float* __restrict__ dst,
                                 int R, int C) {
    __shared__ float tile[32][33];
    int c0 = blockIdx.x * 32, r0 = blockIdx.y * 32;
    int c = c0 + threadIdx.x;
    for (int i = threadIdx.y; i < 32; i += 8) {
        int r = r0 + i;
        if (r < R && c < C) tile[i][threadIdx.x] = src[(size_t)r * C + c];
    }
    __syncthreads();
    int r = r0 + threadIdx.x;
    for (int i = threadIdx.y; i < 32; i += 8) {
        int cc = c0 + i;
        if (cc < C && r < R) dst[(size_t)cc * R + r] = tile[threadIdx.x][i];
    }
}

// fp32 -> (bf16 hi, bf16 lo).  n must be divisible by 4.
__global__ void split_bf16_kernel(const float* __restrict__ src,
                                  __nv_bfloat16* __restrict__ hi,
                                  __nv_bfloat16* __restrict__ lo, int n) {
    int i = (blockIdx.x * blockDim.x + threadIdx.x) * 4;
    if (i < n) {
        float4 v = *(const float4*)(src + i);
        float vv[4] = {v.x, v.y, v.z, v.w};
        __nv_bfloat16 h[4], l[4];
        #pragma unroll
        for (int j = 0; j < 4; j++) {
            h[j] = __float2bfloat16_rn(vv[j]);
            l[j] = __float2bfloat16_rn(vv[j] - __bfloat162float(h[j]));
        }
        *(uint2*)(hi + i) = *(uint2*)h;
        *(uint2*)(lo + i) = *(uint2*)l;
    }
}

// fused cell weights: out (2048, 1024): out[n'][k], n' = d*4+gate, src n = gate*512+d,
// k<512 from srcX, else srcH. hi/lo split inline. grid=2048, block=256 (4 elems/thread).
__global__ void build_cell_w_kernel(const float* __restrict__ srcX, const float* __restrict__ srcH,
                                    __nv_bfloat16* __restrict__ whi, __nv_bfloat16* __restrict__ wlo) {
    int idx = blockIdx.x * 256 + threadIdx.x;
    int e = idx * 4;
    int np = e >> 10, k4 = e & 1023;
    int d = np >> 2, gate = np & 3;
    int n = gate * 512 + d;
    const float* s = (k4 < 512) ? (srcX + (size_t)n * 512 + k4)
                                : (srcH + (size_t)n * 512 + (k4 - 512));
    float4 v = *(const float4*)s;
    float vv[4] = {v.x, v.y, v.z, v.w};
    __nv_bfloat16 h[4], l[4];
    #pragma unroll
    for (int j = 0; j < 4; j++) {
        h[j] = __float2bfloat16_rn(vv[j]);
        l[j] = __float2bfloat16_rn(vv[j] - __bfloat162float(h[j]));
    }
    *(uint2*)(whi + (size_t)np * 1024 + k4) = *(uint2*)h;
    *(uint2*)(wlo + (size_t)np * 1024 + k4) = *(uint2*)l;
}

// =========================================================================
// mma.sync bf16x3 GEMM (templated M-tile):  C(M,N) = A(M,K) * B(N,K)^T (+bias)
// BM = 64*MT, BN = 128, BK = 64. 8 warps (4m x 2n), warp tile (16*MT) x 64.
// grid = (ceil(N/128), M/BM), block = 256.
// =========================================================================
template<int MT>
__global__ __launch_bounds__(256) void gemm_bf16x3_kernel(
    const __nv_bfloat16* __restrict__ Ahi, const __nv_bfloat16* __restrict__ Alo,
    const __nv_bfloat16* __restrict__ Bhi, const __nv_bfloat16* __restrict__ Blo,
    float* __restrict__ C, const float* __restrict__ bias,
    int Mtot, int Ntot, int Ktot)
{
    constexpr int ABYTES = 64 * MT * 128;           // per hi or lo A tile
    constexpr int BUFBYTES = 2 * ABYTES + 32768;    // Ahi+Alo+Bhi+Blo
    extern __shared__ char smem[];
    const uint32_t sb = smem_u32(smem);
    const int tid = threadIdx.x, wid = tid >> 5, lane = tid & 31;
    const int wm = wid & 3, wn = wid >> 2;
    const int m0 = blockIdx.y * (64 * MT), n0 = blockIdx.x * 128;
    const int NT = (Ktot + 63) / 64;

    float acc[MT][8][4];
    #pragma unroll
    for (int mt = 0; mt < MT; mt++)
        #pragma unroll
        for (int nt = 0; nt < 8; nt++)
            #pragma unroll
            for (int j = 0; j < 4; j++) acc[mt][nt][j] = 0.f;

    auto load_chunk = [&](int kt, int buf) {
        const int kc = kt * 64;
        const uint32_t bufbase = sb + buf * BUFBYTES;
        #pragma unroll
        for (int w = 0; w < 2; w++) {
            const __nv_bfloat16* src = w ? Alo : Ahi;
            uint32_t tdst = bufbase + w * ABYTES;
            for (int i = tid; i < 64 * MT * 8; i += 256) {
                int r = i >> 3, c16 = i & 7;
                int gr = m0 + r, gk = kc + c16 * 8;
                bool inb = (gr < Mtot) && (gk < Ktot);
                cp_async16(tdst + SWZ128(r * 128 + c16 * 16),
                           src + (inb ? ((size_t)gr * Ktot + gk) : 0), inb ? 16u : 0u);
            }
        }
        #pragma unroll
        for (int w = 0; w < 2; w++) {
            const __nv_bfloat16* src = w ? Blo : Bhi;
            uint32_t tdst = bufbase + 2 * ABYTES + w * 16384;
            for (int i = tid; i < 1024; i += 256) {
                int r = i >> 3, c16 = i & 7;
                int gr = n0 + r, gk = kc + c16 * 8;
                bool inb = (gr < Ntot) && (gk < Ktot);
                cp_async16(tdst + SWZ128(r * 128 + c16 * 16),
                           src + (inb ? ((size_t)gr * Ktot + gk) : 0), inb ? 16u : 0u);
            }
        }
        CP_COMMIT();
    };

    load_chunk(0, 0);
    const int g8 = lane >> 3, rg = lane & 7;

    for (int kt = 0; kt < NT; kt++) {
        const int buf = kt & 1;
        if (kt + 1 < NT) { load_chunk(kt + 1, buf ^ 1); CP_WAIT(1); }
        else             { CP_WAIT(0); }
        __syncthreads();

        const uint32_t bAh = sb + buf * BUFBYTES;
        const uint32_t bAl = bAh + ABYTES;
        const uint32_t bBh = bAh + 2 * ABYTES;
        const uint32_t bBl = bBh + 16384;

        #pragma unroll
        for (int kk = 0; kk < 4; kk++) {
            const int kb = kk * 32;
            uint32_t ah[MT][4], al[MT][4], bh[8][2], bl[8][2];
            #pragma unroll
            for (int mt = 0; mt < MT; mt++) {
                int row = wm * (16 * MT) + mt * 16 + (g8 & 1) * 8 + rg;
                uint32_t off = SWZ128(row * 128 + kb + (g8 >> 1) * 16);
                ldsm_x4(ah[mt], bAh + off);
                ldsm_x4(al[mt], bAl + off);
            }
            #pragma unroll
            for (int p = 0; p < 4; p++) {
                int rowb = wn * 64 + p * 16 + (g8 >> 1) * 8 + rg;
                uint32_t off = SWZ128(rowb * 128 + kb + (g8 & 1) * 16);
                uint32_t t[4];
                ldsm_x4(t, bBh + off);
                bh[2 * p][0] = t[0]; bh[2 * p][1] = t[1];
                bh[2 * p + 1][0] = t[2]; bh[2 * p + 1][1] = t[3];
                ldsm_x4(t, bBl + off);
                bl[2 * p][0] = t[0]; bl[2 * p][1] = t[1];
                bl[2 * p + 1][0] = t[2]; bl[2 * p + 1][1] = t[3];
            }
            #pragma unroll
            for (int mt = 0; mt < MT; mt++)
                #pragma unroll
                for (int nt = 0; nt < 8; nt++) {
                    mma16816(acc[mt][nt], ah[mt], bh[nt]);
                    mma16816(acc[mt][nt], ah[mt], bl[nt]);
                    mma16816(acc[mt][nt], al[mt], bh[nt]);
                }
        }
        __syncthreads();
    }

    #pragma unroll
    for (int mt = 0; mt < MT; mt++) {
        int row = m0 + wm * (16 * MT) + mt * 16 + (lane >> 2);
        #pragma unroll
        for (int nt = 0; nt < 8; nt++) {
            int col = n0 + wn * 64 + nt * 8 + (lane & 3) * 2;
            if (col < Ntot) {
                float b0 = 0.f, b1 = 0.f;
                if (bias) { b0 = bias[col]; b1 = bias[col + 1]; }
                float2 v0 = make_float2(acc[mt][nt][0] + b0, acc[mt][nt][1] + b1);
                float2 v1 = make_float2(acc[mt][nt][2] + b0, acc[mt][nt][3] + b1);
                *(float2*)&C[(size_t)row * Ntot + col] = v0;
                *(float2*)&C[(size_t)(row + 8) * Ntot + col] = v1;
            }
        }
    }
}

// =========================================================================
// tensor-core LSTM cell (bf16x3): gates(128,2048) = [x|h](128,1024) @ Wc^T
// grid = 128 CTAs (16 gate-interleaved cols = 4 d's each), block = 256 (8 warps).
// smem: per buf {Ahi 16KB, Alo 16KB, Whi 2KB, Wlo 2KB} x2 + gates 8KB = 80KB
// =========================================================================
#define CELL_SMEM (2 * 36864 + 8192)

__global__ __launch_bounds__(256) void lstm_cell_tc_kernel(
    const __nv_bfloat16* __restrict__ Whi, const __nv_bfloat16* __restrict__ Wlo,
    const __nv_bfloat16* __restrict__ xhi, const __nv_bfloat16* __restrict__ xlo,
    const __nv_bfloat16* __restrict__ hhi, const __nv_bfloat16* __restrict__ hlo,
    const float* __restrict__ bias, float* __restrict__ c,
    __nv_bfloat16* __restrict__ outhi, __nv_bfloat16* __restrict__ outlo)
{
    extern __shared__ char smem[];
    const uint32_t sb = smem_u32(smem);
    const int tid = threadIdx.x, wid = tid >> 5, lane = tid & 31;
    const int n0 = blockIdx.x * 16;
    const int kstart = (xhi == nullptr) ? 8 : 0;

    auto load_chunk = [&](int ch, int buf) {
        const __nv_bfloat16 *ah, *al;
        int koff;
        if (ch < 8) { ah = xhi; al = xlo; koff = ch * 64; }
        else        { ah = hhi; al = hlo; koff = (ch - 8) * 64; }
        const uint32_t base = sb + buf * 36864;
        #pragma unroll
        for (int w = 0; w < 2; w++) {
            const __nv_bfloat16* src = w ? al : ah;
            uint32_t tdst = base + w * 16384;
            #pragma unroll
            for (int it = 0; it < 4; it++) {
                int i = it * 256 + tid;
                int r = i >> 3, c16 = i & 7;
                cp_async16(tdst + SWZ128(r * 128 + c16 * 16),
                           src + (size_t)r * 512 + koff + c16 * 8, 16);
            }
        }
        // W chunk: 16 rows x 64 k (hi then lo), 128 ops each
        {
            int half = tid >> 7;            // 0 = hi, 1 = lo
            int t2 = tid & 127;
            int r = t2 >> 3, c16 = t2 & 7;
            const __nv_bfloat16* src = half ? Wlo : Whi;
            uint32_t tdst = base + 32768 + half * 2048;
            cp_async16(tdst + SWZ128(r * 128 + c16 * 16),
                       src + (size_t)(n0 + r) * 1024 + ch * 64 + c16 * 8, 16);
        }
        CP_COMMIT();
    };

    float acc[2][4];
    #pragma unroll
    for (int b = 0; b < 2; b++)
        #pragma unroll
        for (int j = 0; j < 4; j++) acc[b][j] = 0.f;

    load_chunk(kstart, 0);
    const int g8 = lane >> 3, rg = lane & 7;

    for (int ch = kstart; ch < 16; ch++) {
        const int buf = (ch - kstart) & 1;
        if (ch + 1 < 16) { load_chunk(ch + 1, buf ^ 1); CP_WAIT(1); }
        else             { CP_WAIT(0); }
        __syncthreads();

        const uint32_t bA = sb + buf * 36864;
        const uint32_t bAl = bA + 16384, bW = bA + 32768, bWl = bW + 2048;

        #pragma unroll
        for (int kk = 0; kk < 4; kk++) {
            const int kb = kk * 32;
            uint32_t ah[4], al[4], tw[4], twl[4];
            int row = wid * 16 + (g8 & 1) * 8 + rg;
            uint32_t offA = SWZ128(row * 128 + kb + (g8 >> 1) * 16);
            ldsm_x4(ah, bA + offA);
            ldsm_x4(al, bAl + offA);
            int rowb = (g8 >> 1) * 8 + rg;
            uint32_t offB = SWZ128(rowb * 128 + kb + (g8 & 1) * 16);
            ldsm_x4(tw, bW + offB);
            ldsm_x4(twl, bWl + offB);
            uint32_t bh0[2] = {tw[0], tw[1]},  bh1[2] = {tw[2], tw[3]};
            uint32_t bl0[2] = {twl[0], twl[1]}, bl1[2] = {twl[2], twl[3]};
            mma16816(acc[0], ah, bh0);
            mma16816(acc[0], ah, bl0);
            mma16816(acc[0], al, bh0);
            mma16816(acc[1], ah, bh1);
            mma16816(acc[1], ah, bl1);
            mma16816(acc[1], al, bh1);
        }
        __syncthreads();
    }

    // stage gates to smem: (128 rows, 16 cols) fp32
    float* gates = (float*)(smem + 2 * 36864);
    {
        int r0 = wid * 16 + (lane >> 2);
        int cb = (lane & 3) * 2;
        #pragma unroll
        for (int b = 0; b < 2; b++) {
            gates[r0 * 16 + b * 8 + cb]           = acc[b][0];
            gates[r0 * 16 + b * 8 + cb + 1]       = acc[b][1];
            gates[(r0 + 8) * 16 + b * 8 + cb]     = acc[b][2];
            gates[(r0 + 8) * 16 + b * 8 + cb + 1] = acc[b][3];
        }
    }
    __syncthreads();

    // activations: 512 items (128 rows x 4 d's), 2 per thread
    #pragma unroll
    for (int it = 0; it < 2; it++) {
        int idx = it * 256 + tid;
        int row = idx & 127, dd = idx >> 7;
        int d = blockIdx.x * 4 + dd;
        float gi = gates[row * 16 + dd * 4 + 0] + bias[d];
        float gf = gates[row * 16 + dd * 4 + 1] + bias[512 + d];
        float gg = gates[row * 16 + dd * 4 + 2] + bias[1024 + d];
        float go = gates[row * 16 + dd * 4 + 3] + bias[1536 + d];
        float i_ = 1.f / (1.f + expf(-gi));
        float f_ = 1.f / (1.f + expf(-gf));
        float g_ = tanhf(gg);
        float o_ = 1.f / (1.f + expf(-go));
        float cn = f_ * c[row * 512 + d] + i_ * g_;
        c[row * 512 + d] = cn;
        float hv = o_ * tanhf(cn);
        __nv_bfloat16 hh = __float2bfloat16_rn(hv);
        outhi[row * 512 + d] = hh;
        outlo[row * 512 + d] = __float2bfloat16_rn(hv - __bfloat162float(hh));
    }
}

// =========================================================================
// host
// =========================================================================
extern "C" void kernel_launch(void* const* d_in, const int* in_sizes, int n_in,
                              void* d_out, int out_size) {
    const float* input_ = (const float*)d_in[0];
    const float* W_ih0  = (const float*)d_in[1];
    const float* W_hh0  = (const float*)d_in[2];
    const float* b_ih0  = (const float*)d_in[3];
    const float* b_hh0  = (const float*)d_in[4];
    const float* W_ih1  = (const float*)d_in[5];
    const float* W_hh1  = (const float*)d_in[6];
    const float* b_ih1  = (const float*)d_in[7];
    const float* b_hh1  = (const float*)d_in[8];
    const float* W_enc  = (const float*)d_in[9];
    const float* b_enc  = (const float*)d_in[10];
    float* out = (float*)d_out;

    float *p_Mtmp, *p_WencT, *p_c0, *p_c1, *p_bias0, *p_bias0f, *p_bias1;
    __nv_bfloat16 *p_A1hi, *p_A1lo, *p_B1hi, *p_B1lo, *p_B2hi, *p_B2lo, *p_H1hi, *p_H1lo;
    __nv_bfloat16 *p_Wc0hi, *p_Wc0lo, *p_Wc1hi, *p_Wc1lo;
    __nv_bfloat16 *p_h0hiA, *p_h0loA, *p_h0hiB, *p_h0loB, *p_h1zhi, *p_h1zlo;
    cudaGetSymbolAddress((void**)&p_Mtmp,   g_Mtmp);
    cudaGetSymbolAddress((void**)&p_WencT,  g_WencT);
    cudaGetSymbolAddress((void**)&p_c0,     g_c0);
    cudaGetSymbolAddress((void**)&p_c1,     g_c1);
    cudaGetSymbolAddress((void**)&p_bias0,  g_bias0);
    cudaGetSymbolAddress((void**)&p_bias0f, g_bias0f);
    cudaGetSymbolAddress((void**)&p_bias1,  g_bias1);
    cudaGetSymbolAddress((void**)&p_A1hi,   g_A1hi);
    cudaGetSymbolAddress((void**)&p_A1lo,   g_A1lo);
    cudaGetSymbolAddress((void**)&p_B1hi,   g_B1hi);
    cudaGetSymbolAddress((void**)&p_B1lo,   g_B1lo);
    cudaGetSymbolAddress((void**)&p_B2hi,   g_B2hi);
    cudaGetSymbolAddress((void**)&p_B2lo,   g_B2lo);
    cudaGetSymbolAddress((void**)&p_H1hi,   g_H1hi);
    cudaGetSymbolAddress((void**)&p_H1lo,   g_H1lo);
    cudaGetSymbolAddress((void**)&p_Wc0hi,  g_Wc0hi);
    cudaGetSymbolAddress((void**)&p_Wc0lo,  g_Wc0lo);
    cudaGetSymbolAddress((void**)&p_Wc1hi,  g_Wc1hi);
    cudaGetSymbolAddress((void**)&p_Wc1lo,  g_Wc1lo);
    cudaGetSymbolAddress((void**)&p_h0hiA,  g_h0hiA);
    cudaGetSymbolAddress((void**)&p_h0loA,  g_h0loA);
    cudaGetSymbolAddress((void**)&p_h0hiB,  g_h0hiB);
    cudaGetSymbolAddress((void**)&p_h0loB,  g_h0loB);
    cudaGetSymbolAddress((void**)&p_h1zhi,  g_h1zhi);
    cudaGetSymbolAddress((void**)&p_h1zlo,  g_h1zlo);

    cudaFuncSetAttribute(gemm_bf16x3_kernel<1>,
                         cudaFuncAttributeMaxDynamicSharedMemorySize, 2 * (2 * 8192 + 32768));
    cudaFuncSetAttribute(gemm_bf16x3_kernel<2>,
                         cudaFuncAttributeMaxDynamicSharedMemorySize, 2 * (2 * 16384 + 32768));
    cudaFuncSetAttribute(lstm_cell_tc_kernel,
                         cudaFuncAttributeMaxDynamicSharedMemorySize, CELL_SMEM);

    // ---- prep ----
    zero_state_kernel<<<(BB * DD + 255) / 256, 256>>>();
    bias_prep_kernel<<<(GG + 255) / 256, 256>>>(b_ih0, b_hh0, b_ih1, b_hh1);
    bfused_kernel<<<GG, 256>>>(W_ih0, b_enc);

    dim3 tb(32, 8);
    transpose_kernel<<<dim3(512 / 32, (VV + 31) / 32), tb>>>(W_enc, p_WencT, VV, DD);

    {
        int n1 = GG * VV;   // W_ih0
        split_bf16_kernel<<<(n1 / 4 + 255) / 256, 256>>>(W_ih0, p_A1hi, p_A1lo, n1);
        int n2 = DD * VV;   // WencT
        split_bf16_kernel<<<(n2 / 4 + 255) / 256, 256>>>(p_WencT, p_B1hi, p_B1lo, n2);
        int n3 = VV * DD;   // W_enc
        split_bf16_kernel<<<(n3 / 4 + 255) / 256, 256>>>(W_enc, p_B2hi, p_B2lo, n3);
        // initial h0 = input_ (B,D)
        split_bf16_kernel<<<(BB * DD / 4 + 255) / 256, 256>>>(input_, p_h0hiA, p_h0loA, BB * DD);
    }

    // GEMM1: Mtmp(2048,512) = W_ih0(2048,10000) @ WencT(512,10000)^T   [bf16x3, BM=64]
    gemm_bf16x3_kernel<1><<<dim3(DD / 128, GG / 64), 256, 2 * (2 * 8192 + 32768)>>>(
        p_A1hi, p_A1lo, p_B1hi, p_B1lo, p_Mtmp, nullptr, GG, DD, VV);

    // fused, gate-interleaved cell weights
    build_cell_w_kernel<<<2048, 256>>>(p_Mtmp, W_hh0, p_Wc0hi, p_Wc0lo);
    build_cell_w_kernel<<<2048, 256>>>(W_ih1, W_hh1, p_Wc1hi, p_Wc1lo);

    // ---- sequential recurrence (tensor-core cells) ----
    __nv_bfloat16 *h0ih = p_h0hiA, *h0il = p_h0loA;
    __nv_bfloat16 *h0oh = p_h0hiB, *h0ol = p_h0loB;
    for (int t = 0; t < TT; t++) {
        const __nv_bfloat16* xh = (t == 0) ? nullptr : (p_H1hi + (size_t)(t - 1) * BB * DD);
        const __nv_bfloat16* xl = (t == 0) ? nullptr : (p_H1lo + (size_t)(t - 1) * BB * DD);
        const float* bias0 = (t == 0) ? p_bias0 : p_bias0f;
        lstm_cell_tc_kernel<<<128, 256, CELL_SMEM>>>(
            p_Wc0hi, p_Wc0lo, xh, xl, h0ih, h0il, bias0, p_c0, h0oh, h0ol);

        const __nv_bfloat16* h1h = (t == 0) ? p_h1zhi : (p_H1hi + (size_t)(t - 1) * BB * DD);
        const __nv_bfloat16* h1l = (t == 0) ? p_h1zlo : (p_H1lo + (size_t)(t - 1) * BB * DD);
        lstm_cell_tc_kernel<<<128, 256, CELL_SMEM>>>(
            p_Wc1hi, p_Wc1lo, h0oh, h0ol, h1h, h1l, p_bias1, p_c1,
            p_H1hi + (size_t)t * BB * DD, p_H1lo + (size_t)t * BB * DD);

        // swap h0 buffers
        __nv_bfloat16* tmp;
        tmp = h0ih; h0ih = h0oh; h0oh = tmp;
        tmp = h0il; h0il = h0ol; h0ol = tmp;
    }

    // GEMM2: OUT(2560,10000) = H1(2560,512) @ W_enc(10000,512)^T + b_enc  [bf16x3, BM=128]
    gemm_bf16x3_kernel<2><<<dim3((VV + 127) / 128, (TT * BB) / 128), 256, 2 * (2 * 16384 + 32768)>>>(
        p_H1hi, p_H1lo, p_B2hi, p_B2lo, out, b_enc, TT * BB, VV, DD);
}

// round 6
// speedup vs baseline: 3.5357x; 1.1118x over previous
#include <cuda_runtime.h>
#include <cuda_bf16.h>
#include <math.h>
#include <stdint.h>

#define BB 128     // batch
#define DD 512     // hidden
#define GG 2048    // 4*D
#define VV 10000   // vocab
#define TT 20      // timesteps
#define NCTA 128   // persistent kernel CTAs

// ---------------- device scratch (no allocation allowed) ----------------
__device__ float g_Mtmp[GG * DD];    // (2048,512)  W_ih0 @ W_enc (fp32)
__device__ float g_WencT[DD * VV];   // (512,10000) fp32 transpose of W_enc
__device__ float g_bias0[GG];
__device__ float g_bias0f[GG];
__device__ float g_bias1[GG];
__device__ unsigned g_bar;           // grid barrier counter (reset each launch)
// bf16 hi/lo operand buffers
__device__ __nv_bfloat16 g_A1hi[(size_t)GG * VV];  // W_ih0 (2048,10000)
__device__ __nv_bfloat16 g_A1lo[(size_t)GG * VV];
__device__ __nv_bfloat16 g_B1hi[(size_t)DD * VV];  // WencT rows=512, K=10000
__device__ __nv_bfloat16 g_B1lo[(size_t)DD * VV];
__device__ __nv_bfloat16 g_B2hi[(size_t)VV * DD];  // W_enc rows=10000, K=512
__device__ __nv_bfloat16 g_B2lo[(size_t)VV * DD];
__device__ __nv_bfloat16 g_H1hi[TT * BB * DD];     // h1 history
__device__ __nv_bfloat16 g_H1lo[TT * BB * DD];
// fused, gate-interleaved cell weights: (2048 rows n'=d*4+gate, K=1024 = [x|h])
__device__ __nv_bfloat16 g_Wc0hi[(size_t)GG * 1024];
__device__ __nv_bfloat16 g_Wc0lo[(size_t)GG * 1024];
__device__ __nv_bfloat16 g_Wc1hi[(size_t)GG * 1024];
__device__ __nv_bfloat16 g_Wc1lo[(size_t)GG * 1024];
// h0 double buffers + zero-h1 (bf16 hi/lo)
__device__ __nv_bfloat16 g_h0hiA[BB * DD], g_h0loA[BB * DD];
__device__ __nv_bfloat16 g_h0hiB[BB * DD], g_h0loB[BB * DD];
__device__ __nv_bfloat16 g_h1zhi[BB * DD], g_h1zlo[BB * DD];

// =========================================================================
// helpers
// =========================================================================
__device__ __forceinline__ uint32_t smem_u32(const void* p) {
    uint32_t a;
    asm("{ .reg .u64 t; cvta.to.shared.u64 t, %1; cvt.u32.u64 %0, t; }" : "=r"(a) : "l"(p));
    return a;
}
#define SWZ128(o) ((o) ^ (((o) >> 3) & 0x70))

__device__ __forceinline__ void ldsm_x4(uint32_t* r, uint32_t addr) {
    asm volatile("ldmatrix.sync.aligned.m8n8.x4.shared.b16 {%0,%1,%2,%3}, [%4];"
                 : "=r"(r[0]), "=r"(r[1]), "=r"(r[2]), "=r"(r[3]) : "r"(addr));
}
__device__ __forceinline__ void mma16816(float* d, const uint32_t* a, const uint32_t* b) {
    asm volatile(
        "mma.sync.aligned.m16n8k16.row.col.f32.bf16.bf16.f32 "
        "{%0,%1,%2,%3}, {%4,%5,%6,%7}, {%8,%9}, {%0,%1,%2,%3};"
        : "+f"(d[0]), "+f"(d[1]), "+f"(d[2]), "+f"(d[3])
        : "r"(a[0]), "r"(a[1]), "r"(a[2]), "r"(a[3]), "r"(b[0]), "r"(b[1]));
}
__device__ __forceinline__ void cp_async16(uint32_t daddr, const void* g, unsigned sz) {
    asm volatile("cp.async.cg.shared.global [%0], [%1], 16, %2;"
                 :: "r"(daddr), "l"(g), "r"(sz));
}
#define CP_COMMIT() asm volatile("cp.async.commit_group;" ::: "memory")
#define CP_WAIT(n)  asm volatile("cp.async.wait_group %0;" :: "n"(n) : "memory")

// =========================================================================
// prep kernels
// =========================================================================
__global__ void zero_state_kernel() {
    int i = blockIdx.x * blockDim.x + threadIdx.x;
    if (i == 0) g_bar = 0u;
    if (i < BB * DD) {
        g_h1zhi[i] = __float2bfloat16_rn(0.f);
        g_h1zlo[i] = __float2bfloat16_rn(0.f);
    }
}

__global__ void bias_prep_kernel(const float* __restrict__ b_ih0, const float* __restrict__ b_hh0,
                                 const float* __restrict__ b_ih1, const float* __restrict__ b_hh1) {
    int g = blockIdx.x * blockDim.x + threadIdx.x;
    if (g < GG) {
        g_bias0[g] = b_ih0[g] + b_hh0[g];
        g_bias1[g] = b_ih1[g] + b_hh1[g];
    }
}

__global__ void bfused_kernel(const float* __restrict__ W_ih0, const float* __restrict__ b_enc) {
    __shared__ float red[256];
    int g = blockIdx.x;
    float s = 0.f;
    for (int v = threadIdx.x; v < VV; v += 256)
        s += W_ih0[(size_t)g * VV + v] * b_enc[v];
    red[threadIdx.x] = s;
    __syncthreads();
    for (int o = 128; o > 0; o >>= 1) {
        if (threadIdx.x < o) red[threadIdx.x] += red[threadIdx.x + o];
        __syncthreads();
    }
    if (threadIdx.x == 0) g_bias0f[g] = g_bias0[g] + red[0];
}

__global__ void transpose_kernel(const float* __restrict__ src, float* __restrict__ dst,
                                 int R, int C) {
    __shared__ float tile[32][33];
    int c0 = blockIdx.x * 32, r0 = blockIdx.y * 32;
    int c = c0 + threadIdx.x;
    for (int i = threadIdx.y; i < 32; i += 8) {
        int r = r0 + i;
        if (r < R && c < C) tile[i][threadIdx.x] = src[(size_t)r * C + c];
    }
    __syncthreads();
    int r = r0 + threadIdx.x;
    for (int i = threadIdx.y; i < 32; i += 8) {
        int cc = c0 + i;
        if (cc < C && r < R) dst[(size_t)cc * R + r] = tile[threadIdx.x][i];
    }
}

// fp32 -> (bf16 hi, bf16 lo).  n must be divisible by 4.
__global__ void split_bf16_kernel(const float* __restrict__ src,
                                  __nv_bfloat16* __restrict__ hi,
                                  __nv_bfloat16* __restrict__ lo, int n) {
    int i = (blockIdx.x * blockDim.x + threadIdx.x) * 4;
    if (i < n) {
        float4 v = *(const float4*)(src + i);
        float vv[4] = {v.x, v.y, v.z, v.w};
        __nv_bfloat16 h[4], l[4];
        #pragma unroll
        for (int j = 0; j < 4; j++) {
            h[j] = __float2bfloat16_rn(vv[j]);
            l[j] = __float2bfloat16_rn(vv[j] - __bfloat162float(h[j]));
        }
        *(uint2*)(hi + i) = *(uint2*)h;
        *(uint2*)(lo + i) = *(uint2*)l;
    }
}

// fused cell weights: out (2048,1024): n' = d*4+gate, src n = gate*512+d,
// k<512 from srcX else srcH. grid=2048, block=256.
__global__ void build_cell_w_kernel(const float* __restrict__ srcX, const float* __restrict__ srcH,
                                    __nv_bfloat16* __restrict__ whi, __nv_bfloat16* __restrict__ wlo) {
    int idx = blockIdx.x * 256 + threadIdx.x;
    int e = idx * 4;
    int np = e >> 10, k4 = e & 1023;
    int d = np >> 2, gate = np & 3;
    int n = gate * 512 + d;
    const float* s = (k4 < 512) ? (srcX + (size_t)n * 512 + k4)
                                : (srcH + (size_t)n * 512 + (k4 - 512));
    float4 v = *(const float4*)s;
    float vv[4] = {v.x, v.y, v.z, v.w};
    __nv_bfloat16 h[4], l[4];
    #pragma unroll
    for (int j = 0; j < 4; j++) {
        h[j] = __float2bfloat16_rn(vv[j]);
        l[j] = __float2bfloat16_rn(vv[j] - __bfloat162float(h[j]));
    }
    *(uint2*)(whi + (size_t)np * 1024 + k4) = *(uint2*)h;
    *(uint2*)(wlo + (size_t)np * 1024 + k4) = *(uint2*)l;
}

// =========================================================================
// mma.sync bf16x3 GEMM:  C(M,N) = A(M,K) * B(N,K)^T (+bias)
// BM = MW*MT*16, BN = 128, BK = 64. MW*2 warps (MW in m, 2 in n).
// =========================================================================
template<int MT, int MW>
__global__ __launch_bounds__(MW * 64) void gemm_bf16x3_kernel(
    const __nv_bfloat16* __restrict__ Ahi, const __nv_bfloat16* __restrict__ Alo,
    const __nv_bfloat16* __restrict__ Bhi, const __nv_bfloat16* __restrict__ Blo,
    float* __restrict__ C, const float* __restrict__ bias,
    int Mtot, int Ntot, int Ktot)
{
    constexpr int BM = MW * MT * 16;
    constexpr int NTH = MW * 64;
    constexpr int ABYTES = BM * 128;
    constexpr int BUFBYTES = 2 * ABYTES + 32768;
    extern __shared__ char smem[];
    const uint32_t sb = smem_u32(smem);
    const int tid = threadIdx.x, wid = tid >> 5, lane = tid & 31;
    const int wm = wid % MW, wn = wid / MW;
    const int m0 = blockIdx.y * BM, n0 = blockIdx.x * 128;
    const int NT = (Ktot + 63) / 64;

    float acc[MT][8][4];
    #pragma unroll
    for (int mt = 0; mt < MT; mt++)
        #pragma unroll
        for (int nt = 0; nt < 8; nt++)
            #pragma unroll
            for (int j = 0; j < 4; j++) acc[mt][nt][j] = 0.f;

    auto load_chunk = [&](int kt, int buf) {
        const int kc = kt * 64;
        const uint32_t bufbase = sb + buf * BUFBYTES;
        #pragma unroll
        for (int w = 0; w < 2; w++) {
            const __nv_bfloat16* src = w ? Alo : Ahi;
            uint32_t tdst = bufbase + w * ABYTES;
            for (int i = tid; i < BM * 8; i += NTH) {
                int r = i >> 3, c16 = i & 7;
                int gr = m0 + r, gk = kc + c16 * 8;
                bool inb = (gr < Mtot) && (gk < Ktot);
                cp_async16(tdst + SWZ128(r * 128 + c16 * 16),
                           src + (inb ? ((size_t)gr * Ktot + gk) : 0), inb ? 16u : 0u);
            }
        }
        #pragma unroll
        for (int w = 0; w < 2; w++) {
            const __nv_bfloat16* src = w ? Blo : Bhi;
            uint32_t tdst = bufbase + 2 * ABYTES + w * 16384;
            for (int i = tid; i < 1024; i += NTH) {
                int r = i >> 3, c16 = i & 7;
                int gr = n0 + r, gk = kc + c16 * 8;
                bool inb = (gr < Ntot) && (gk < Ktot);
                cp_async16(tdst + SWZ128(r * 128 + c16 * 16),
                           src + (inb ? ((size_t)gr * Ktot + gk) : 0), inb ? 16u : 0u);
            }
        }
        CP_COMMIT();
    };

    load_chunk(0, 0);
    const int g8 = lane >> 3, rg = lane & 7;

    for (int kt = 0; kt < NT; kt++) {
        const int buf = kt & 1;
        if (kt + 1 < NT) { load_chunk(kt + 1, buf ^ 1); CP_WAIT(1); }
        else             { CP_WAIT(0); }
        __syncthreads();

        const uint32_t bAh = sb + buf * BUFBYTES;
        const uint32_t bAl = bAh + ABYTES;
        const uint32_t bBh = bAh + 2 * ABYTES;
        const uint32_t bBl = bBh + 16384;

        #pragma unroll
        for (int kk = 0; kk < 4; kk++) {
            const int kb = kk * 32;
            uint32_t ah[MT][4], al[MT][4], bh[8][2], bl[8][2];
            #pragma unroll
            for (int mt = 0; mt < MT; mt++) {
                int row = wm * (16 * MT) + mt * 16 + (g8 & 1) * 8 + rg;
                uint32_t off = SWZ128(row * 128 + kb + (g8 >> 1) * 16);
                ldsm_x4(ah[mt], bAh + off);
                ldsm_x4(al[mt], bAl + off);
            }
            #pragma unroll
            for (int p = 0; p < 4; p++) {
                int rowb = wn * 64 + p * 16 + (g8 >> 1) * 8 + rg;
                uint32_t off = SWZ128(rowb * 128 + kb + (g8 & 1) * 16);
                uint32_t t[4];
                ldsm_x4(t, bBh + off);
                bh[2 * p][0] = t[0]; bh[2 * p][1] = t[1];
                bh[2 * p + 1][0] = t[2]; bh[2 * p + 1][1] = t[3];
                ldsm_x4(t, bBl + off);
                bl[2 * p][0] = t[0]; bl[2 * p][1] = t[1];
                bl[2 * p + 1][0] = t[2]; bl[2 * p + 1][1] = t[3];
            }
            #pragma unroll
            for (int mt = 0; mt < MT; mt++)
                #pragma unroll
                for (int nt = 0; nt < 8; nt++) {
                    mma16816(acc[mt][nt], ah[mt], bh[nt]);
                    mma16816(acc[mt][nt], ah[mt], bl[nt]);
                    mma16816(acc[mt][nt], al[mt], bh[nt]);
                }
        }
        __syncthreads();
    }

    #pragma unroll
    for (int mt = 0; mt < MT; mt++) {
        int row = m0 + wm * (16 * MT) + mt * 16 + (lane >> 2);
        #pragma unroll
        for (int nt = 0; nt < 8; nt++) {
            int col = n0 + wn * 64 + nt * 8 + (lane & 3) * 2;
            if (col < Ntot) {
                float b0 = 0.f, b1 = 0.f;
                if (bias) { b0 = bias[col]; b1 = bias[col + 1]; }
                float2 v0 = make_float2(acc[mt][nt][0] + b0, acc[mt][nt][1] + b1);
                float2 v1 = make_float2(acc[mt][nt][2] + b0, acc[mt][nt][3] + b1);
                *(float2*)&C[(size_t)row * Ntot + col] = v0;
                *(float2*)&C[(size_t)(row + 8) * Ntot + col] = v1;
            }
        }
    }
}

// =========================================================================
// persistent LSTM recurrence: all TT steps x 2 layers in ONE launch.
// 128 CTAs x 256 threads; CTA b owns gate rows n0 = b*16 (d in [b*4, b*4+4)).
// smem: W0 hi/lo 64KB | W1 hi/lo 64KB | A dbuf 64KB | gates 8KB = 200KB
// grid barrier: monotonic atomic counter (reset per launch by zero_state).
// =========================================================================
#define PSM_W0 0
#define PSM_W1 65536
#define PSM_A  131072
#define PSM_G  196608
#define PERS_SMEM 204800

__global__ __launch_bounds__(256) void lstm_persistent_kernel(
    const __nv_bfloat16* __restrict__ Wc0hi, const __nv_bfloat16* __restrict__ Wc0lo,
    const __nv_bfloat16* __restrict__ Wc1hi, const __nv_bfloat16* __restrict__ Wc1lo,
    __nv_bfloat16* __restrict__ h0hiA, __nv_bfloat16* __restrict__ h0loA,
    __nv_bfloat16* __restrict__ h0hiB, __nv_bfloat16* __restrict__ h0loB,
    const __nv_bfloat16* __restrict__ h1zhi, const __nv_bfloat16* __restrict__ h1zlo,
    __nv_bfloat16* __restrict__ H1hi, __nv_bfloat16* __restrict__ H1lo,
    const float* __restrict__ bias0, const float* __restrict__ bias0f,
    const float* __restrict__ bias1)
{
    extern __shared__ char smem[];
    const uint32_t sb = smem_u32(smem);
    float* gates = (float*)(smem + PSM_G);
    const int tid = threadIdx.x, wid = tid >> 5, lane = tid & 31;
    const int n0 = blockIdx.x * 16;
    const int g8 = lane >> 3, rg = lane & 7;

    // ---- load both layers' weight slices into smem (persistent) ----
    {
        const __nv_bfloat16* srcs[4] = {Wc0hi, Wc0lo, Wc1hi, Wc1lo};
        const uint32_t dsts[4] = {PSM_W0, PSM_W0 + 32768, PSM_W1, PSM_W1 + 32768};
        #pragma unroll
        for (int w = 0; w < 4; w++) {
            const __nv_bfloat16* src = srcs[w];
            #pragma unroll
            for (int it = 0; it < 8; it++) {
                int i = it * 256 + tid;
                int ch = i >> 7, r = (i >> 3) & 15, c16 = i & 7;
                cp_async16(sb + dsts[w] + ch * 2048 + SWZ128(r * 128 + c16 * 16),
                           src + (size_t)(n0 + r) * 1024 + ch * 64 + c16 * 8, 16);
            }
        }
        CP_COMMIT();
    }

    // ---- hoisted bias registers (thread owns (row=idx>>2, dd=idx&3), it in {0,1}) ----
    float rb0[2][4], rb0f[2][4], rb1[2][4];
    #pragma unroll
    for (int it = 0; it < 2; it++) {
        int idx = it * 256 + tid;
        int dd = idx & 3;
        int d = blockIdx.x * 4 + dd;
        #pragma unroll
        for (int gte = 0; gte < 4; gte++) {
            rb0[it][gte]  = bias0[gte * 512 + d];
            rb0f[it][gte] = bias0f[gte * 512 + d];
            rb1[it][gte]  = bias1[gte * 512 + d];
        }
    }

    float c0r[2] = {0.f, 0.f}, c1r[2] = {0.f, 0.f};
    unsigned epoch = 0;
    int cur = 0;   // h0 buffer: 0=A, 1=B

    for (int t = 0; t < TT; t++) {
        #pragma unroll
        for (int layer = 0; layer < 2; layer++) {
            // ---- operand selection ----
            const __nv_bfloat16 *xh, *xl, *hh, *hl;
            int kstart;
            if (layer == 0) {
                kstart = (t == 0) ? 8 : 0;
                xh = (t == 0) ? (const __nv_bfloat16*)0 : H1hi + (size_t)(t - 1) * BB * DD;
                xl = (t == 0) ? (const __nv_bfloat16*)0 : H1lo + (size_t)(t - 1) * BB * DD;
                hh = cur ? h0hiB : h0hiA;
                hl = cur ? h0loB : h0loA;
            } else {
                kstart = 0;
                xh = cur ? h0hiA : h0hiB;   // new h0 (written by layer 0)
                xl = cur ? h0loA : h0loB;
                hh = (t == 0) ? h1zhi : H1hi + (size_t)(t - 1) * BB * DD;
                hl = (t == 0) ? h1zlo : H1lo + (size_t)(t - 1) * BB * DD;
            }
            const uint32_t wbase = sb + (layer ? PSM_W1 : PSM_W0);

            auto load_chunk = [&](int ch, int buf) {
                const __nv_bfloat16* ah = (ch < 8) ? xh : hh;
                const __nv_bfloat16* al = (ch < 8) ? xl : hl;
                int koff = (ch & 7) * 64;
                const uint32_t base = sb + PSM_A + buf * 32768;
                #pragma unroll
                for (int w = 0; w < 2; w++) {
                    const __nv_bfloat16* src = w ? al : ah;
                    uint32_t tdst = base + w * 16384;
                    #pragma unroll
                    for (int it = 0; it < 4; it++) {
                        int i = it * 256 + tid;
                        int r = i >> 3, c16 = i & 7;
                        cp_async16(tdst + SWZ128(r * 128 + c16 * 16),
                                   src + (size_t)r * 512 + koff + c16 * 8, 16);
                    }
                }
                CP_COMMIT();
            };

            float acc[2][4];
            #pragma unroll
            for (int b = 0; b < 2; b++)
                #pragma unroll
                for (int j = 0; j < 4; j++) acc[b][j] = 0.f;

            load_chunk(kstart, 0);
            for (int ch = kstart; ch < 16; ch++) {
                const int buf = (ch - kstart) & 1;
                if (ch + 1 < 16) { load_chunk(ch + 1, buf ^ 1); CP_WAIT(1); }
                else             { CP_WAIT(0); }
                __syncthreads();

                const uint32_t bA = sb + PSM_A + buf * 32768;
                const uint32_t bAl = bA + 16384;
                const uint32_t bW = wbase + ch * 2048;
                const uint32_t bWl = bW + 32768;

                #pragma unroll
                for (int kk = 0; kk < 4; kk++) {
                    const int kb = kk * 32;
                    uint32_t ah4[4], al4[4], tw[4], twl[4];
                    int row = wid * 16 + (g8 & 1) * 8 + rg;
                    uint32_t offA = SWZ128(row * 128 + kb + (g8 >> 1) * 16);
                    ldsm_x4(ah4, bA + offA);
                    ldsm_x4(al4, bAl + offA);
                    int rowb = (g8 >> 1) * 8 + rg;
                    uint32_t offB = SWZ128(rowb * 128 + kb + (g8 & 1) * 16);
                    ldsm_x4(tw, bW + offB);
                    ldsm_x4(twl, bWl + offB);
                    uint32_t bh0[2] = {tw[0], tw[1]},  bh1[2] = {tw[2], tw[3]};
                    uint32_t bl0[2] = {twl[0], twl[1]}, bl1[2] = {twl[2], twl[3]};
                    mma16816(acc[0], ah4, bh0);
                    mma16816(acc[0], ah4, bl0);
                    mma16816(acc[0], al4, bh0);
                    mma16816(acc[1], ah4, bh1);
                    mma16816(acc[1], ah4, bl1);
                    mma16816(acc[1], al4, bh1);
                }
                __syncthreads();
            }

            // ---- stage gates to smem ----
            {
                int r0 = wid * 16 + (lane >> 2);
                int cb = (lane & 3) * 2;
                #pragma unroll
                for (int b = 0; b < 2; b++) {
                    gates[r0 * 16 + b * 8 + cb]           = acc[b][0];
                    gates[r0 * 16 + b * 8 + cb + 1]       = acc[b][1];
                    gates[(r0 + 8) * 16 + b * 8 + cb]     = acc[b][2];
                    gates[(r0 + 8) * 16 + b * 8 + cb + 1] = acc[b][3];
                }
            }
            __syncthreads();

            // ---- activations (thread owns (row = idx>>2, dd = idx&3)) ----
            __nv_bfloat16* oh;
            __nv_bfloat16* ol;
            if (layer == 0) {
                oh = cur ? h0hiA : h0hiB;  ol = cur ? h0loA : h0loB;
            } else {
                oh = H1hi + (size_t)t * BB * DD;  ol = H1lo + (size_t)t * BB * DD;
            }
            #pragma unroll
            for (int it = 0; it < 2; it++) {
                int idx = it * 256 + tid;
                int row = idx >> 2, dd = idx & 3;
                int d = blockIdx.x * 4 + dd;
                const float* rb = (layer == 0) ? ((t == 0) ? rb0[it] : rb0f[it]) : rb1[it];
                float gi = gates[row * 16 + dd * 4 + 0] + rb[0];
                float gf = gates[row * 16 + dd * 4 + 1] + rb[1];
                float gg = gates[row * 16 + dd * 4 + 2] + rb[2];
                float go = gates[row * 16 + dd * 4 + 3] + rb[3];
                float i_ = 1.f / (1.f + expf(-gi));
                float f_ = 1.f / (1.f + expf(-gf));
                float g_ = tanhf(gg);
                float o_ = 1.f / (1.f + expf(-go));
                float* cr = (layer == 0) ? &c0r[it] : &c1r[it];
                float cn = f_ * (*cr) + i_ * g_;
                *cr = cn;
                float hv = o_ * tanhf(cn);
                __nv_bfloat16 hhv = __float2bfloat16_rn(hv);
                oh[row * 512 + d] = hhv;
                ol[row * 512 + d] = __float2bfloat16_rn(hv - __bfloat162float(hhv));
            }

            // ---- grid barrier ----
            __threadfence();
            __syncthreads();
            epoch++;
            if (tid == 0) {
                atomicAdd(&g_bar, 1u);
                unsigned target = epoch * NCTA;
                volatile unsigned* p = &g_bar;
                while (*p < target) { }
                __threadfence();
            }
            __syncthreads();
        }
        cur ^= 1;
    }
}

// =========================================================================
// host
// =========================================================================
extern "C" void kernel_launch(void* const* d_in, const int* in_sizes, int n_in,
                              void* d_out, int out_size) {
    const float* input_ = (const float*)d_in[0];
    const float* W_ih0  = (const float*)d_in[1];
    const float* W_hh0  = (const float*)d_in[2];
    const float* b_ih0  = (const float*)d_in[3];
    const float* b_hh0  = (const float*)d_in[4];
    const float* W_ih1  = (const float*)d_in[5];
    const float* W_hh1  = (const float*)d_in[6];
    const float* b_ih1  = (const float*)d_in[7];
    const float* b_hh1  = (const float*)d_in[8];
    const float* W_enc  = (const float*)d_in[9];
    const float* b_enc  = (const float*)d_in[10];
    float* out = (float*)d_out;

    float *p_Mtmp, *p_WencT, *p_bias0, *p_bias0f, *p_bias1;
    __nv_bfloat16 *p_A1hi, *p_A1lo, *p_B1hi, *p_B1lo, *p_B2hi, *p_B2lo, *p_H1hi, *p_H1lo;
    __nv_bfloat16 *p_Wc0hi, *p_Wc0lo, *p_Wc1hi, *p_Wc1lo;
    __nv_bfloat16 *p_h0hiA, *p_h0loA, *p_h0hiB, *p_h0loB, *p_h1zhi, *p_h1zlo;
    cudaGetSymbolAddress((void**)&p_Mtmp,   g_Mtmp);
    cudaGetSymbolAddress((void**)&p_WencT,  g_WencT);
    cudaGetSymbolAddress((void**)&p_bias0,  g_bias0);
    cudaGetSymbolAddress((void**)&p_bias0f, g_bias0f);
    cudaGetSymbolAddress((void**)&p_bias1,  g_bias1);
    cudaGetSymbolAddress((void**)&p_A1hi,   g_A1hi);
    cudaGetSymbolAddress((void**)&p_A1lo,   g_A1lo);
    cudaGetSymbolAddress((void**)&p_B1hi,   g_B1hi);
    cudaGetSymbolAddress((void**)&p_B1lo,   g_B1lo);
    cudaGetSymbolAddress((void**)&p_B2hi,   g_B2hi);
    cudaGetSymbolAddress((void**)&p_B2lo,   g_B2lo);
    cudaGetSymbolAddress((void**)&p_H1hi,   g_H1hi);
    cudaGetSymbolAddress((void**)&p_H1lo,   g_H1lo);
    cudaGetSymbolAddress((void**)&p_Wc0hi,  g_Wc0hi);
    cudaGetSymbolAddress((void**)&p_Wc0lo,  g_Wc0lo);
    cudaGetSymbolAddress((void**)&p_Wc1hi,  g_Wc1hi);
    cudaGetSymbolAddress((void**)&p_Wc1lo,  g_Wc1lo);
    cudaGetSymbolAddress((void**)&p_h0hiA,  g_h0hiA);
    cudaGetSymbolAddress((void**)&p_h0loA,  g_h0loA);
    cudaGetSymbolAddress((void**)&p_h0hiB,  g_h0hiB);
    cudaGetSymbolAddress((void**)&p_h0loB,  g_h0loB);
    cudaGetSymbolAddress((void**)&p_h1zhi,  g_h1zhi);
    cudaGetSymbolAddress((void**)&p_h1zlo,  g_h1zlo);

    cudaFuncSetAttribute((const void*)gemm_bf16x3_kernel<1, 4>,
                         cudaFuncAttributeMaxDynamicSharedMemorySize, 98304);
    cudaFuncSetAttribute((const void*)gemm_bf16x3_kernel<2, 8>,
                         cudaFuncAttributeMaxDynamicSharedMemorySize, 196608);
    cudaFuncSetAttribute((const void*)lstm_persistent_kernel,
                         cudaFuncAttributeMaxDynamicSharedMemorySize, PERS_SMEM);

    // ---- prep ----
    zero_state_kernel<<<(BB * DD + 255) / 256, 256>>>();
    bias_prep_kernel<<<(GG + 255) / 256, 256>>>(b_ih0, b_hh0, b_ih1, b_hh1);
    bfused_kernel<<<GG, 256>>>(W_ih0, b_enc);

    dim3 tb(32, 8);
    transpose_kernel<<<dim3(512 / 32, (VV + 31) / 32), tb>>>(W_enc, p_WencT, VV, DD);

    {
        int n1 = GG * VV;
        split_bf16_kernel<<<(n1 / 4 + 255) / 256, 256>>>(W_ih0, p_A1hi, p_A1lo, n1);
        int n2 = DD * VV;
        split_bf16_kernel<<<(n2 / 4 + 255) / 256, 256>>>(p_WencT, p_B1hi, p_B1lo, n2);
        int n3 = VV * DD;
        split_bf16_kernel<<<(n3 / 4 + 255) / 256, 256>>>(W_enc, p_B2hi, p_B2lo, n3);
        split_bf16_kernel<<<(BB * DD / 4 + 255) / 256, 256>>>(input_, p_h0hiA, p_h0loA, BB * DD);
    }

    // GEMM1: Mtmp(2048,512) = W_ih0 @ WencT^T   [bf16x3, BM=64, grid 128]
    gemm_bf16x3_kernel<1, 4><<<dim3(DD / 128, GG / 64), 256, 98304>>>(
        p_A1hi, p_A1lo, p_B1hi, p_B1lo, p_Mtmp, nullptr, GG, DD, VV);

    // fused, gate-interleaved cell weights
    build_cell_w_kernel<<<2048, 256>>>(p_Mtmp, W_hh0, p_Wc0hi, p_Wc0lo);
    build_cell_w_kernel<<<2048, 256>>>(W_ih1, W_hh1, p_Wc1hi, p_Wc1lo);

    // ---- entire recurrence in one persistent launch ----
    lstm_persistent_kernel<<<NCTA, 256, PERS_SMEM>>>(
        p_Wc0hi, p_Wc0lo, p_Wc1hi, p_Wc1lo,
        p_h0hiA, p_h0loA, p_h0hiB, p_h0loB,
        p_h1zhi, p_h1zlo, p_H1hi, p_H1lo,
        p_bias0, p_bias0f, p_bias1);

    // GEMM2: OUT(2560,10000) = H1 @ W_enc^T + b_enc  [bf16x3, BM=256, 512 thr]
    gemm_bf16x3_kernel<2, 8><<<dim3((VV + 127) / 128, (TT * BB) / 256), 512, 196608>>>(
        p_H1hi, p_H1lo, p_B2hi, p_B2lo, out, b_enc, TT * BB, VV, DD);
}